// round 6
// baseline (speedup 1.0000x reference)
#include <cuda_runtime.h>

#define NPOINTS     500000
#define NWAVE       128
#define NOFFSETS    50

#define TPB         128
#define NBLK        1480            // 10 blocks/SM on 148 SMs
#define TILE        128
#define QUOT        337             // NPOINTS / NBLK
#define REMR        1240            // NPOINTS - QUOT*NBLK

#define RGRID       185             // reduce blocks; 185 * 8 = 1480
#define RCHUNK      8

#define TWO_PI      6.283185307179586f

// Accum-coalesced layout [block][wave].
__device__ float g_partialC[NBLK * NWAVE];
__device__ float g_partialS[NBLK * NWAVE];
// Stage-1 reduce output [rblock][wave].
__device__ float g2C[RGRID * NWAVE];
__device__ float g2S[RGRID * NWAVE];
__device__ unsigned int g_cnt;      // zero-init; finisher resets each run

__global__ __launch_bounds__(TPB, 10)
void accum_kernel(const float2* __restrict__ xy,
                  const float*  __restrict__ tid,
                  const float*  __restrict__ center,
                  const float*  __restrict__ wavelength)
{
    __shared__ float sdist[TILE];

    const int w  = threadIdx.x;
    const float kw = TWO_PI / wavelength[w];
    const float cx = center[0];
    const float cy = center[1];

    // Balanced contiguous range: blocks differ by at most 1 point of work.
    const int b    = blockIdx.x;
    const int base = b * QUOT + min(b, REMR);
    const int cnt  = QUOT + (b < REMR ? 1 : 0);

    float accC = 0.0f;
    float accS = 0.0f;

    for (int t0 = 0; t0 < cnt; t0 += TILE) {
        const int n = min(TILE, cnt - t0);

        // Phase A: cooperatively compute dist for this tile of points.
        if (threadIdx.x < n) {
            const float2 v = xy[base + t0 + threadIdx.x];
            const float dx = v.x - cx;
            const float dy = v.y - cy;
            sdist[threadIdx.x] = sqrtf(fmaf(dx, dx, dy * dy));
        }
        __syncthreads();

        // Phase B: sweep the tile for this thread's wavelength.
        const float* __restrict__ trow = tid + (size_t)(base + t0) * NWAVE + w;

        #pragma unroll 8
        for (int i = 0; i < n; i++) {
            const float t = __ldcs(trow + (size_t)i * NWAVE);  // coalesced row read
            float s, c;
            __sincosf(sdist[i] * kw, &s, &c);                  // 2x MUFU
            accC = fmaf(c, t, accC);
            accS = fmaf(s, t, accS);
        }
        __syncthreads();
    }

    g_partialC[b * NWAVE + w] = accC;    // coalesced row store
    g_partialS[b * NWAVE + w] = accS;
}

// Tail: 185 blocks each sum an 8-row chunk of partials (all accesses
// warp-coalesced against the [block][wave] layout, fixed order). The last
// block to finish reduces the 185-row intermediate and writes the output.
__global__ __launch_bounds__(NWAVE)
void reduce_kernel(float* __restrict__ out)
{
    __shared__ float sm2[NWAVE];
    __shared__ unsigned int is_last;

    const int w  = threadIdx.x;
    const int b0 = blockIdx.x * RCHUNK;

    float c = 0.0f, s = 0.0f;
    #pragma unroll
    for (int j = 0; j < RCHUNK; j++) {            // coalesced 512B rows
        c += g_partialC[(b0 + j) * NWAVE + w];
        s += g_partialS[(b0 + j) * NWAVE + w];
    }
    g2C[blockIdx.x * NWAVE + w] = c;              // coalesced
    g2S[blockIdx.x * NWAVE + w] = s;

    __threadfence();
    if (w == 0)
        is_last = (atomicAdd(&g_cnt, 1u) == RGRID - 1) ? 1u : 0u;
    __syncthreads();

    if (!is_last) return;

    // Final: sum 185 rows (coalesced, L2-hot), fixed order -> deterministic.
    float sc = 0.0f, ss = 0.0f;
    #pragma unroll 8
    for (int r = 0; r < RGRID; r++) {
        sc += g2C[r * NWAVE + w];
        ss += g2S[r * NWAVE + w];
    }
    const float C = sc * (1.0f / (float)NPOINTS);
    const float S = ss * (1.0f / (float)NPOINTS);

    float m = -3.402823466e38f;
    #pragma unroll
    for (int i = 0; i < NOFFSETS; i++) {
        const float o = (float)i * (TWO_PI / (float)(NOFFSETS - 1));
        const float v = C * cosf(o) - S * sinf(o);
        m = fmaxf(m, v);
    }
    sm2[w] = m;
    __syncthreads();

    #pragma unroll
    for (int stride = NWAVE / 2; stride > 0; stride >>= 1) {
        if (w < stride) sm2[w] += sm2[w + stride];
        __syncthreads();
    }
    if (w == 0) {
        out[0] = -sm2[0];
        g_cnt = 0;                 // reset for next graph replay
    }
}

extern "C" void kernel_launch(void* const* d_in, const int* in_sizes, int n_in,
                              void* d_out, int out_size)
{
    const float2* xy         = (const float2*)d_in[0];  // [500000, 2]
    const float*  tid        = (const float*) d_in[1];  // [500000, 128]
    const float*  center     = (const float*) d_in[2];  // [2]
    const float*  wavelength = (const float*) d_in[3];  // [128]
    float* out = (float*)d_out;

    accum_kernel<<<NBLK, TPB>>>(xy, tid, center, wavelength);
    reduce_kernel<<<RGRID, NWAVE>>>(out);
}